// round 6
// baseline (speedup 1.0000x reference)
#include <cuda_runtime.h>
#include <cstdint>

#define NMAX 50000
#define EMAX 400000
#define HEADS 4
#define DIM 64
#define HD 256   // HEADS*DIM

// ---------------- scratch (device globals; no allocation) ----------------
__device__ float g_xh   [(size_t)NMAX * HD];    // projected features [N,256]
__device__ float g_agg  [(size_t)NMAX * HD];    // aggregated messages [N,256]
__device__ float g_alpha[(size_t)EMAX * HEADS]; // exp(leaky_relu) per edge [E,4]
__device__ float g_denom[(size_t)NMAX * HEADS]; // softmax denominators [N,4]
__device__ float g_ssrc [(size_t)NMAX * HEADS];
__device__ float g_sdst [(size_t)NMAX * HEADS];

// ---------------- vector red helper ----------------
__device__ __forceinline__ void red_add_v4(float* ptr, float a, float b, float c, float d) {
    asm volatile("red.global.add.v4.f32 [%0], {%1,%2,%3,%4};"
                 :: "l"(ptr), "f"(a), "f"(b), "f"(c), "f"(d) : "memory");
}

// ---------------- zero-init agg + denom ----------------
__global__ void k_zero(float* __restrict__ agg, float* __restrict__ denom, int n) {
    int idx = blockIdx.x * blockDim.x + threadIdx.x;
    int tot4 = n * (HD / 4);
    for (int t = idx; t < tot4; t += gridDim.x * blockDim.x)
        ((float4*)agg)[t] = make_float4(0.f, 0.f, 0.f, 0.f);
    if (idx < n)
        ((float4*)denom)[idx] = make_float4(0.f, 0.f, 0.f, 0.f);
}

// ---------------- GEMM1: xh = x @ W_lin^T, fused attention scores ----------------
// K=64 fixed. blockIdx.y = head. Each block: 64 rows x 64 cols (one head).
// Epilogue computes s_src/s_dst per (row, head) via 16-lane butterfly.
__global__ __launch_bounds__(256) void k_gemm1(
    const float* __restrict__ A,     // x [M,64]
    const float* __restrict__ B,     // W_lin [256,64]
    const float* __restrict__ asrc,  // [4,64]
    const float* __restrict__ adst,  // [4,64]
    float* __restrict__ C,           // xh [M,256]
    float* __restrict__ ssrc, float* __restrict__ sdst, int M)
{
    __shared__ float As[64][68];
    __shared__ float Bs[64][68];
    const int t  = threadIdx.x;
    const int m0 = blockIdx.x * 64;
    const int h  = blockIdx.y;
    const float* Bt = B + (size_t)h * 64 * DIM;
    const int cg = (t & 15) * 4;
    const int rg = (t >> 4) * 4;
    float acc[4][4] = {};

    #pragma unroll
    for (int it = 0; it < 4; ++it) {
        int lin = t + it * 256;
        int r  = lin >> 4;
        int k4 = (lin & 15) * 4;
        float4 v = make_float4(0.f, 0.f, 0.f, 0.f);
        int gr = m0 + r;
        if (gr < M) v = *(const float4*)(A + (size_t)gr * DIM + k4);
        *(float4*)&As[r][k4] = v;
    }
    #pragma unroll
    for (int it = 0; it < 4; ++it) {
        int lin = t + it * 256;
        int c  = lin >> 4;
        int k4 = (lin & 15) * 4;
        float4 v = *(const float4*)(Bt + (size_t)c * DIM + k4);
        Bs[k4 + 0][c] = v.x; Bs[k4 + 1][c] = v.y;
        Bs[k4 + 2][c] = v.z; Bs[k4 + 3][c] = v.w;
    }
    __syncthreads();
    #pragma unroll
    for (int k = 0; k < 64; ++k) {
        float4 b4 = *(const float4*)&Bs[k][cg];
        float a0 = As[rg + 0][k];
        float a1 = As[rg + 1][k];
        float a2 = As[rg + 2][k];
        float a3 = As[rg + 3][k];
        acc[0][0] += a0 * b4.x; acc[0][1] += a0 * b4.y; acc[0][2] += a0 * b4.z; acc[0][3] += a0 * b4.w;
        acc[1][0] += a1 * b4.x; acc[1][1] += a1 * b4.y; acc[1][2] += a1 * b4.z; acc[1][3] += a1 * b4.w;
        acc[2][0] += a2 * b4.x; acc[2][1] += a2 * b4.y; acc[2][2] += a2 * b4.z; acc[2][3] += a2 * b4.w;
        acc[3][0] += a3 * b4.x; acc[3][1] += a3 * b4.y; acc[3][2] += a3 * b4.z; acc[3][3] += a3 * b4.w;
    }

    // store xh
    #pragma unroll
    for (int i = 0; i < 4; ++i) {
        int gr = m0 + rg + i;
        if (gr < M) {
            float4 v = make_float4(acc[i][0], acc[i][1], acc[i][2], acc[i][3]);
            *(float4*)(C + (size_t)gr * HD + h * 64 + cg) = v;
        }
    }

    // fused scores: s[row] = dot(xh[row, h*64: h*64+64], attn[h])
    float4 va = __ldg((const float4*)(asrc + h * DIM + cg));
    float4 vd = __ldg((const float4*)(adst + h * DIM + cg));
    float ss[4], sd[4];
    #pragma unroll
    for (int i = 0; i < 4; ++i) {
        ss[i] = acc[i][0] * va.x + acc[i][1] * va.y + acc[i][2] * va.z + acc[i][3] * va.w;
        sd[i] = acc[i][0] * vd.x + acc[i][1] * vd.y + acc[i][2] * vd.z + acc[i][3] * vd.w;
    }
    #pragma unroll
    for (int o = 1; o < 16; o <<= 1) {
        #pragma unroll
        for (int i = 0; i < 4; ++i) {
            ss[i] += __shfl_xor_sync(0xffffffffu, ss[i], o);
            sd[i] += __shfl_xor_sync(0xffffffffu, sd[i], o);
        }
    }
    if ((t & 15) == 0) {
        #pragma unroll
        for (int i = 0; i < 4; ++i) {
            int gr = m0 + rg + i;
            if (gr < M) {
                ssrc[(size_t)gr * HEADS + h] = ss[i];
                sdst[(size_t)gr * HEADS + h] = sd[i];
            }
        }
    }
}

// ---------------- per-edge: alpha_exp + denominator atomics ----------------
__global__ void k_edge_alpha(const int* __restrict__ ei,
                             const float* __restrict__ ssrc, const float* __restrict__ sdst,
                             float* __restrict__ alpha, float* __restrict__ denom, int E)
{
    int e = blockIdx.x * blockDim.x + threadIdx.x;
    if (e >= E) return;
    int i = ei[e];        // dst
    int j = ei[E + e];    // src
    float4 sd = *(const float4*)(sdst + (size_t)i * 4);
    float4 ss = *(const float4*)(ssrc + (size_t)j * 4);
    float a0 = sd.x + ss.x; a0 = a0 > 0.f ? a0 : 0.2f * a0;
    float a1 = sd.y + ss.y; a1 = a1 > 0.f ? a1 : 0.2f * a1;
    float a2 = sd.z + ss.z; a2 = a2 > 0.f ? a2 : 0.2f * a2;
    float a3 = sd.w + ss.w; a3 = a3 > 0.f ? a3 : 0.2f * a3;
    float e0 = expf(a0), e1 = expf(a1), e2 = expf(a2), e3 = expf(a3);
    *(float4*)(alpha + (size_t)e * 4) = make_float4(e0, e1, e2, e3);
    red_add_v4(denom + (size_t)i * 4, e0, e1, e2, e3);
}

// ---------------- per-edge aggregation: one warp per edge ----------------
__global__ __launch_bounds__(256) void k_edge_agg(
    const int* __restrict__ ei,
    const float* __restrict__ alpha, const float* __restrict__ denom,
    const float* __restrict__ xh, float* __restrict__ agg, int E)
{
    int w    = (blockIdx.x * blockDim.x + threadIdx.x) >> 5;
    int lane = threadIdx.x & 31;
    if (w >= E) return;
    int i = ei[w];        // dst
    int j = ei[E + w];    // src
    float4 al = *(const float4*)(alpha + (size_t)w * 4);
    float4 dn = *(const float4*)(denom + (size_t)i * 4);
    float wh[4];
    wh[0] = al.x / (dn.x + 1e-9f);
    wh[1] = al.y / (dn.y + 1e-9f);
    wh[2] = al.z / (dn.z + 1e-9f);
    wh[3] = al.w / (dn.w + 1e-9f);
    const float* src = xh + (size_t)j * HD;
    float* dst = agg + (size_t)i * HD;
    #pragma unroll
    for (int it = 0; it < 2; ++it) {
        int f = it * 128 + lane * 4;
        float s = wh[f >> 6];
        float4 v = *(const float4*)(src + f);
        red_add_v4(dst + f, v.x * s, v.y * s, v.z * s, v.w * s);
    }
}

// ---------------- GEMM2: out = LN(ELU(agg @ W_out^T + b) + x) ----------------
// K=256. Each block: 64 rows x 64 cols (full output width). LN fused.
__global__ __launch_bounds__(256) void k_gemm2(
    const float* __restrict__ A,     // agg [M,256]
    const float* __restrict__ B,     // W_out [64,256]
    const float* __restrict__ x,     // residual [M,64]
    const float* __restrict__ bias,
    const float* __restrict__ lng, const float* __restrict__ lnb,
    float* __restrict__ out, int M)
{
    __shared__ float As[64][68];
    __shared__ float Bs[64][68];
    const int t  = threadIdx.x;
    const int m0 = blockIdx.x * 64;
    const int cg = (t & 15) * 4;
    const int rg = (t >> 4) * 4;
    float acc[4][4] = {};

    for (int kc = 0; kc < HD; kc += 64) {
        #pragma unroll
        for (int it = 0; it < 4; ++it) {
            int lin = t + it * 256;
            int r  = lin >> 4;
            int k4 = (lin & 15) * 4;
            float4 v = make_float4(0.f, 0.f, 0.f, 0.f);
            int gr = m0 + r;
            if (gr < M) v = *(const float4*)(A + (size_t)gr * HD + kc + k4);
            *(float4*)&As[r][k4] = v;
        }
        #pragma unroll
        for (int it = 0; it < 4; ++it) {
            int lin = t + it * 256;
            int c  = lin >> 4;
            int k4 = (lin & 15) * 4;
            float4 v = *(const float4*)(B + (size_t)c * HD + kc + k4);
            Bs[k4 + 0][c] = v.x; Bs[k4 + 1][c] = v.y;
            Bs[k4 + 2][c] = v.z; Bs[k4 + 3][c] = v.w;
        }
        __syncthreads();
        #pragma unroll
        for (int k = 0; k < 64; ++k) {
            float4 b4 = *(const float4*)&Bs[k][cg];
            float a0 = As[rg + 0][k];
            float a1 = As[rg + 1][k];
            float a2 = As[rg + 2][k];
            float a3 = As[rg + 3][k];
            acc[0][0] += a0 * b4.x; acc[0][1] += a0 * b4.y; acc[0][2] += a0 * b4.z; acc[0][3] += a0 * b4.w;
            acc[1][0] += a1 * b4.x; acc[1][1] += a1 * b4.y; acc[1][2] += a1 * b4.z; acc[1][3] += a1 * b4.w;
            acc[2][0] += a2 * b4.x; acc[2][1] += a2 * b4.y; acc[2][2] += a2 * b4.z; acc[2][3] += a2 * b4.w;
            acc[3][0] += a3 * b4.x; acc[3][1] += a3 * b4.y; acc[3][2] += a3 * b4.z; acc[3][3] += a3 * b4.w;
        }
        __syncthreads();
    }

    // fused epilogue: bias + ELU + residual, then LayerNorm per row
    float4 bv = __ldg((const float4*)(bias + cg));
    float bb[4] = {bv.x, bv.y, bv.z, bv.w};
    float ls[4], lq[4];
    #pragma unroll
    for (int i = 0; i < 4; ++i) {
        int gr = m0 + rg + i;
        float4 xr = make_float4(0.f, 0.f, 0.f, 0.f);
        if (gr < M) xr = *(const float4*)(x + (size_t)gr * DIM + cg);
        float xa[4] = {xr.x, xr.y, xr.z, xr.w};
        float s = 0.f, q = 0.f;
        #pragma unroll
        for (int c = 0; c < 4; ++c) {
            float v = acc[i][c] + bb[c];
            v = v > 0.f ? v : (expf(v) - 1.0f);   // ELU alpha=1
            float y = v + xa[c];
            acc[i][c] = y;
            s += y; q += y * y;
        }
        ls[i] = s; lq[i] = q;
    }
    #pragma unroll
    for (int o = 1; o < 16; o <<= 1) {
        #pragma unroll
        for (int i = 0; i < 4; ++i) {
            ls[i] += __shfl_xor_sync(0xffffffffu, ls[i], o);
            lq[i] += __shfl_xor_sync(0xffffffffu, lq[i], o);
        }
    }
    float4 gv = __ldg((const float4*)(lng + cg));
    float4 bvv = __ldg((const float4*)(lnb + cg));
    float gg[4] = {gv.x, gv.y, gv.z, gv.w};
    float lb[4] = {bvv.x, bvv.y, bvv.z, bvv.w};
    #pragma unroll
    for (int i = 0; i < 4; ++i) {
        int gr = m0 + rg + i;
        if (gr < M) {
            float mu  = ls[i] * (1.0f / 64.0f);
            float var = lq[i] * (1.0f / 64.0f) - mu * mu;
            float inv = rsqrtf(var + 1e-5f);
            float4 v;
            v.x = (acc[i][0] - mu) * inv * gg[0] + lb[0];
            v.y = (acc[i][1] - mu) * inv * gg[1] + lb[1];
            v.z = (acc[i][2] - mu) * inv * gg[2] + lb[2];
            v.w = (acc[i][3] - mu) * inv * gg[3] + lb[3];
            *(float4*)(out + (size_t)gr * DIM + cg) = v;
        }
    }
}

// ---------------- launch ----------------
extern "C" void kernel_launch(void* const* d_in, const int* in_sizes, int n_in,
                              void* d_out, int out_size)
{
    const float* x    = (const float*)d_in[0];
    const int*   ei   = (const int*)d_in[1];   // int32 [2,E] (JAX demotes int64)
    const float* Wlin = (const float*)d_in[2];
    const float* asrc = (const float*)d_in[3];
    const float* adst = (const float*)d_in[4];
    const float* Wout = (const float*)d_in[5];
    const float* bout = (const float*)d_in[6];
    const float* lng  = (const float*)d_in[7];
    const float* lnb  = (const float*)d_in[8];
    float*       out  = (float*)d_out;

    int n = in_sizes[0] / DIM;
    int E = in_sizes[1] / 2;
    if (n > NMAX) n = NMAX;
    if (E > EMAX) E = EMAX;

    float *p_xh, *p_agg, *p_alpha, *p_denom, *p_ssrc, *p_sdst;
    cudaGetSymbolAddress((void**)&p_xh,    g_xh);
    cudaGetSymbolAddress((void**)&p_agg,   g_agg);
    cudaGetSymbolAddress((void**)&p_alpha, g_alpha);
    cudaGetSymbolAddress((void**)&p_denom, g_denom);
    cudaGetSymbolAddress((void**)&p_ssrc,  g_ssrc);
    cudaGetSymbolAddress((void**)&p_sdst,  g_sdst);

    // 1) zero agg + denom
    k_zero<<<(n * (HD / 4) + 255) / 256, 256>>>(p_agg, p_denom, n);

    // 2) xh = x @ W_lin^T with fused s_src/s_dst
    dim3 g1((n + 63) / 64, HEADS);
    k_gemm1<<<g1, 256>>>(x, Wlin, asrc, adst, p_xh, p_ssrc, p_sdst, n);

    // 3) per-edge exp(leaky_relu) + denominator
    k_edge_alpha<<<(E + 255) / 256, 256>>>(ei, p_ssrc, p_sdst, p_alpha, p_denom, E);

    // 4) per-edge weighted aggregation (warp per edge, vector atomics)
    k_edge_agg<<<(E + 7) / 8, 256>>>(ei, p_alpha, p_denom, p_xh, p_agg, E);

    // 5) out = LN(ELU(agg @ W_out^T + b) + x)  — fused epilogue
    k_gemm2<<<(n + 63) / 64, 256>>>(p_agg, Wout, x, bout, lng, lnb, out, n);
}

// round 8
// speedup vs baseline: 1.0130x; 1.0130x over previous
#include <cuda_runtime.h>
#include <cstdint>

#define NMAX 50000
#define EMAX 400000
#define HEADS 4
#define DIM 64
#define HD 256   // HEADS*DIM

// ---------------- scratch (device globals; no allocation) ----------------
__device__ float g_xh    [(size_t)NMAX * HD];     // projected features [N,256]
__device__ float g_agg   [(size_t)NMAX * HD];     // aggregated messages [N,256]
__device__ float g_ssrc  [(size_t)NMAX * HEADS];
__device__ float g_sdst  [(size_t)NMAX * HEADS];
__device__ int   g_cnt   [NMAX];                  // dst-degree histogram
__device__ int   g_off   [NMAX + 1];              // CSR offsets
__device__ int   g_cursor[NMAX];                  // scatter cursors
__device__ int   g_esrc  [EMAX];                  // src node per sorted edge
__device__ float g_ealpha[(size_t)EMAX * HEADS];  // alpha_exp per sorted edge [*,4]

// ---------------- zero histogram ----------------
__global__ void k_hzero(int* __restrict__ cnt, int n) {
    int i = blockIdx.x * blockDim.x + threadIdx.x;
    if (i < n) cnt[i] = 0;
}

// ---------------- histogram of dst ----------------
__global__ void k_hist(const int* __restrict__ ei, int* __restrict__ cnt, int E) {
    int e = blockIdx.x * blockDim.x + threadIdx.x;
    if (e < E) atomicAdd(&cnt[ei[e]], 1);
}

// ---------------- single-block exclusive scan (n up to NMAX) ----------------
__global__ __launch_bounds__(1024) void k_scan(const int* __restrict__ cnt,
                                               int* __restrict__ off,
                                               int* __restrict__ cursor, int n)
{
    __shared__ int warpsum[32];
    const int tid  = threadIdx.x;
    const int lane = tid & 31;
    const int wid  = tid >> 5;
    int base = 0;
    for (int chunk = 0; chunk < n; chunk += 1024) {
        int idx = chunk + tid;
        int v = (idx < n) ? cnt[idx] : 0;
        // inclusive warp scan
        int x = v;
        #pragma unroll
        for (int o = 1; o < 32; o <<= 1) {
            int y = __shfl_up_sync(0xffffffffu, x, o);
            if (lane >= o) x += y;
        }
        if (lane == 31) warpsum[wid] = x;
        __syncthreads();
        if (wid == 0) {
            int w = (lane < 32) ? warpsum[lane] : 0;
            #pragma unroll
            for (int o = 1; o < 32; o <<= 1) {
                int y = __shfl_up_sync(0xffffffffu, w, o);
                if (lane >= o) w += y;
            }
            warpsum[lane] = w;
        }
        __syncthreads();
        int excl = x - v + (wid > 0 ? warpsum[wid - 1] : 0) + base;
        if (idx < n) { off[idx] = excl; cursor[idx] = excl; }
        int total = warpsum[31];
        __syncthreads();   // protect warpsum before next chunk overwrites
        base += total;
    }
    if (tid == 0) off[n] = base;
}

// ---------------- GEMM1: xh = x @ W_lin^T, fused attention scores ----------------
__global__ __launch_bounds__(256) void k_gemm1(
    const float* __restrict__ A,     // x [M,64]
    const float* __restrict__ B,     // W_lin [256,64]
    const float* __restrict__ asrc,  // [4,64]
    const float* __restrict__ adst,  // [4,64]
    float* __restrict__ C,           // xh [M,256]
    float* __restrict__ ssrc, float* __restrict__ sdst, int M)
{
    __shared__ float As[64][68];
    __shared__ float Bs[64][68];
    const int t  = threadIdx.x;
    const int m0 = blockIdx.x * 64;
    const int h  = blockIdx.y;
    const float* Bt = B + (size_t)h * 64 * DIM;
    const int cg = (t & 15) * 4;
    const int rg = (t >> 4) * 4;
    float acc[4][4] = {};

    #pragma unroll
    for (int it = 0; it < 4; ++it) {
        int lin = t + it * 256;
        int r  = lin >> 4;
        int k4 = (lin & 15) * 4;
        float4 v = make_float4(0.f, 0.f, 0.f, 0.f);
        int gr = m0 + r;
        if (gr < M) v = *(const float4*)(A + (size_t)gr * DIM + k4);
        *(float4*)&As[r][k4] = v;
    }
    #pragma unroll
    for (int it = 0; it < 4; ++it) {
        int lin = t + it * 256;
        int c  = lin >> 4;
        int k4 = (lin & 15) * 4;
        float4 v = *(const float4*)(Bt + (size_t)c * DIM + k4);
        Bs[k4 + 0][c] = v.x; Bs[k4 + 1][c] = v.y;
        Bs[k4 + 2][c] = v.z; Bs[k4 + 3][c] = v.w;
    }
    __syncthreads();
    #pragma unroll
    for (int k = 0; k < 64; ++k) {
        float4 b4 = *(const float4*)&Bs[k][cg];
        float a0 = As[rg + 0][k];
        float a1 = As[rg + 1][k];
        float a2 = As[rg + 2][k];
        float a3 = As[rg + 3][k];
        acc[0][0] += a0 * b4.x; acc[0][1] += a0 * b4.y; acc[0][2] += a0 * b4.z; acc[0][3] += a0 * b4.w;
        acc[1][0] += a1 * b4.x; acc[1][1] += a1 * b4.y; acc[1][2] += a1 * b4.z; acc[1][3] += a1 * b4.w;
        acc[2][0] += a2 * b4.x; acc[2][1] += a2 * b4.y; acc[2][2] += a2 * b4.z; acc[2][3] += a2 * b4.w;
        acc[3][0] += a3 * b4.x; acc[3][1] += a3 * b4.y; acc[3][2] += a3 * b4.z; acc[3][3] += a3 * b4.w;
    }

    #pragma unroll
    for (int i = 0; i < 4; ++i) {
        int gr = m0 + rg + i;
        if (gr < M) {
            float4 v = make_float4(acc[i][0], acc[i][1], acc[i][2], acc[i][3]);
            *(float4*)(C + (size_t)gr * HD + h * 64 + cg) = v;
        }
    }

    float4 va = __ldg((const float4*)(asrc + h * DIM + cg));
    float4 vd = __ldg((const float4*)(adst + h * DIM + cg));
    float ss[4], sd[4];
    #pragma unroll
    for (int i = 0; i < 4; ++i) {
        ss[i] = acc[i][0] * va.x + acc[i][1] * va.y + acc[i][2] * va.z + acc[i][3] * va.w;
        sd[i] = acc[i][0] * vd.x + acc[i][1] * vd.y + acc[i][2] * vd.z + acc[i][3] * vd.w;
    }
    #pragma unroll
    for (int o = 1; o < 16; o <<= 1) {
        #pragma unroll
        for (int i = 0; i < 4; ++i) {
            ss[i] += __shfl_xor_sync(0xffffffffu, ss[i], o);
            sd[i] += __shfl_xor_sync(0xffffffffu, sd[i], o);
        }
    }
    if ((t & 15) == 0) {
        #pragma unroll
        for (int i = 0; i < 4; ++i) {
            int gr = m0 + rg + i;
            if (gr < M) {
                ssrc[(size_t)gr * HEADS + h] = ss[i];
                sdst[(size_t)gr * HEADS + h] = sd[i];
            }
        }
    }
}

// ---------------- scatter edges into dst-sorted order, alpha computed inline ----------------
__global__ void k_scatter(const int* __restrict__ ei,
                          const float* __restrict__ ssrc, const float* __restrict__ sdst,
                          int* __restrict__ cursor,
                          int* __restrict__ esrc, float* __restrict__ ealpha, int E)
{
    int e = blockIdx.x * blockDim.x + threadIdx.x;
    if (e >= E) return;
    int i = ei[e];        // dst
    int j = ei[E + e];    // src
    float4 sd = *(const float4*)(sdst + (size_t)i * 4);
    float4 ss = *(const float4*)(ssrc + (size_t)j * 4);
    float a0 = sd.x + ss.x; a0 = a0 > 0.f ? a0 : 0.2f * a0;
    float a1 = sd.y + ss.y; a1 = a1 > 0.f ? a1 : 0.2f * a1;
    float a2 = sd.z + ss.z; a2 = a2 > 0.f ? a2 : 0.2f * a2;
    float a3 = sd.w + ss.w; a3 = a3 > 0.f ? a3 : 0.2f * a3;
    int pos = atomicAdd(&cursor[i], 1);
    esrc[pos] = j;
    *(float4*)(ealpha + (size_t)pos * 4) =
        make_float4(expf(a0), expf(a1), expf(a2), expf(a3));
}

// ---------------- CSR aggregation: one warp per dst node ----------------
// lane covers 8 contiguous floats of the 256-float row; head = lane>>3.
__global__ __launch_bounds__(256) void k_agg_csr(
    const int* __restrict__ off, const int* __restrict__ esrc,
    const float* __restrict__ ealpha, const float* __restrict__ xh,
    float* __restrict__ agg, int n)
{
    int w    = (blockIdx.x * blockDim.x + threadIdx.x) >> 5;
    int lane = threadIdx.x & 31;
    if (w >= n) return;
    int beg = off[w], end = off[w + 1];
    int head = lane >> 3;                    // 8 lanes per head
    float acc0 = 0.f, acc1 = 0.f, acc2 = 0.f, acc3 = 0.f;
    float acc4 = 0.f, acc5 = 0.f, acc6 = 0.f, acc7 = 0.f;
    float dsum = 0.f;

    int e = beg;
    int j = 0; float a = 0.f;
    if (e < end) { j = esrc[e]; a = ealpha[(size_t)e * 4 + head]; }
    while (e < end) {
        int jn = 0; float an = 0.f;
        if (e + 1 < end) { jn = esrc[e + 1]; an = ealpha[(size_t)(e + 1) * 4 + head]; }
        const float* s = xh + (size_t)j * HD + lane * 8;
        float4 v0 = *(const float4*)(s);
        float4 v1 = *(const float4*)(s + 4);
        acc0 += a * v0.x; acc1 += a * v0.y; acc2 += a * v0.z; acc3 += a * v0.w;
        acc4 += a * v1.x; acc5 += a * v1.y; acc6 += a * v1.z; acc7 += a * v1.w;
        dsum += a;
        j = jn; a = an; ++e;
    }
    float inv = 1.0f / (dsum + 1e-9f);
    float* d = agg + (size_t)w * HD + lane * 8;
    *(float4*)(d)     = make_float4(acc0 * inv, acc1 * inv, acc2 * inv, acc3 * inv);
    *(float4*)(d + 4) = make_float4(acc4 * inv, acc5 * inv, acc6 * inv, acc7 * inv);
}

// ---------------- GEMM2: out = LN(ELU(agg @ W_out^T + b) + x) ----------------
__global__ __launch_bounds__(256) void k_gemm2(
    const float* __restrict__ A,     // agg [M,256]
    const float* __restrict__ B,     // W_out [64,256]
    const float* __restrict__ x,     // residual [M,64]
    const float* __restrict__ bias,
    const float* __restrict__ lng, const float* __restrict__ lnb,
    float* __restrict__ out, int M)
{
    __shared__ float As[64][68];
    __shared__ float Bs[64][68];
    const int t  = threadIdx.x;
    const int m0 = blockIdx.x * 64;
    const int cg = (t & 15) * 4;
    const int rg = (t >> 4) * 4;
    float acc[4][4] = {};

    for (int kc = 0; kc < HD; kc += 64) {
        #pragma unroll
        for (int it = 0; it < 4; ++it) {
            int lin = t + it * 256;
            int r  = lin >> 4;
            int k4 = (lin & 15) * 4;
            float4 v = make_float4(0.f, 0.f, 0.f, 0.f);
            int gr = m0 + r;
            if (gr < M) v = *(const float4*)(A + (size_t)gr * HD + kc + k4);
            *(float4*)&As[r][k4] = v;
        }
        #pragma unroll
        for (int it = 0; it < 4; ++it) {
            int lin = t + it * 256;
            int c  = lin >> 4;
            int k4 = (lin & 15) * 4;
            float4 v = *(const float4*)(B + (size_t)c * HD + kc + k4);
            Bs[k4 + 0][c] = v.x; Bs[k4 + 1][c] = v.y;
            Bs[k4 + 2][c] = v.z; Bs[k4 + 3][c] = v.w;
        }
        __syncthreads();
        #pragma unroll
        for (int k = 0; k < 64; ++k) {
            float4 b4 = *(const float4*)&Bs[k][cg];
            float a0 = As[rg + 0][k];
            float a1 = As[rg + 1][k];
            float a2 = As[rg + 2][k];
            float a3 = As[rg + 3][k];
            acc[0][0] += a0 * b4.x; acc[0][1] += a0 * b4.y; acc[0][2] += a0 * b4.z; acc[0][3] += a0 * b4.w;
            acc[1][0] += a1 * b4.x; acc[1][1] += a1 * b4.y; acc[1][2] += a1 * b4.z; acc[1][3] += a1 * b4.w;
            acc[2][0] += a2 * b4.x; acc[2][1] += a2 * b4.y; acc[2][2] += a2 * b4.z; acc[2][3] += a2 * b4.w;
            acc[3][0] += a3 * b4.x; acc[3][1] += a3 * b4.y; acc[3][2] += a3 * b4.z; acc[3][3] += a3 * b4.w;
        }
        __syncthreads();
    }

    float4 bv = __ldg((const float4*)(bias + cg));
    float bb[4] = {bv.x, bv.y, bv.z, bv.w};
    float ls[4], lq[4];
    #pragma unroll
    for (int i = 0; i < 4; ++i) {
        int gr = m0 + rg + i;
        float4 xr = make_float4(0.f, 0.f, 0.f, 0.f);
        if (gr < M) xr = *(const float4*)(x + (size_t)gr * DIM + cg);
        float xa[4] = {xr.x, xr.y, xr.z, xr.w};
        float s = 0.f, q = 0.f;
        #pragma unroll
        for (int c = 0; c < 4; ++c) {
            float v = acc[i][c] + bb[c];
            v = v > 0.f ? v : (expf(v) - 1.0f);   // ELU alpha=1
            float y = v + xa[c];
            acc[i][c] = y;
            s += y; q += y * y;
        }
        ls[i] = s; lq[i] = q;
    }
    #pragma unroll
    for (int o = 1; o < 16; o <<= 1) {
        #pragma unroll
        for (int i = 0; i < 4; ++i) {
            ls[i] += __shfl_xor_sync(0xffffffffu, ls[i], o);
            lq[i] += __shfl_xor_sync(0xffffffffu, lq[i], o);
        }
    }
    float4 gv  = __ldg((const float4*)(lng + cg));
    float4 bvv = __ldg((const float4*)(lnb + cg));
    float gg[4] = {gv.x, gv.y, gv.z, gv.w};
    float lb[4] = {bvv.x, bvv.y, bvv.z, bvv.w};
    #pragma unroll
    for (int i = 0; i < 4; ++i) {
        int gr = m0 + rg + i;
        if (gr < M) {
            float mu  = ls[i] * (1.0f / 64.0f);
            float var = lq[i] * (1.0f / 64.0f) - mu * mu;
            float inv = rsqrtf(var + 1e-5f);
            float4 v;
            v.x = (acc[i][0] - mu) * inv * gg[0] + lb[0];
            v.y = (acc[i][1] - mu) * inv * gg[1] + lb[1];
            v.z = (acc[i][2] - mu) * inv * gg[2] + lb[2];
            v.w = (acc[i][3] - mu) * inv * gg[3] + lb[3];
            *(float4*)(out + (size_t)gr * DIM + cg) = v;
        }
    }
}

// ---------------- launch ----------------
extern "C" void kernel_launch(void* const* d_in, const int* in_sizes, int n_in,
                              void* d_out, int out_size)
{
    const float* x    = (const float*)d_in[0];
    const int*   ei   = (const int*)d_in[1];   // int32 [2,E]
    const float* Wlin = (const float*)d_in[2];
    const float* asrc = (const float*)d_in[3];
    const float* adst = (const float*)d_in[4];
    const float* Wout = (const float*)d_in[5];
    const float* bout = (const float*)d_in[6];
    const float* lng  = (const float*)d_in[7];
    const float* lnb  = (const float*)d_in[8];
    float*       out  = (float*)d_out;

    int n = in_sizes[0] / DIM;
    int E = in_sizes[1] / 2;
    if (n > NMAX) n = NMAX;
    if (E > EMAX) E = EMAX;

    float *p_xh, *p_agg, *p_ssrc, *p_sdst, *p_ealpha;
    int *p_cnt, *p_off, *p_cursor, *p_esrc;
    cudaGetSymbolAddress((void**)&p_xh,     g_xh);
    cudaGetSymbolAddress((void**)&p_agg,    g_agg);
    cudaGetSymbolAddress((void**)&p_ssrc,   g_ssrc);
    cudaGetSymbolAddress((void**)&p_sdst,   g_sdst);
    cudaGetSymbolAddress((void**)&p_cnt,    g_cnt);
    cudaGetSymbolAddress((void**)&p_off,    g_off);
    cudaGetSymbolAddress((void**)&p_cursor, g_cursor);
    cudaGetSymbolAddress((void**)&p_esrc,   g_esrc);
    cudaGetSymbolAddress((void**)&p_ealpha, g_ealpha);

    // 1) dst-degree histogram
    k_hzero<<<(n + 255) / 256, 256>>>(p_cnt, n);
    k_hist <<<(E + 255) / 256, 256>>>(ei, p_cnt, E);

    // 2) CSR offsets (single-block scan) — overlapped logically with gemm1 on stream
    k_scan<<<1, 1024>>>(p_cnt, p_off, p_cursor, n);

    // 3) xh = x @ W_lin^T with fused s_src/s_dst
    dim3 g1((n + 63) / 64, HEADS);
    k_gemm1<<<g1, 256>>>(x, Wlin, asrc, adst, p_xh, p_ssrc, p_sdst, n);

    // 4) scatter edges into dst-sorted order with inline alpha
    k_scatter<<<(E + 255) / 256, 256>>>(ei, p_ssrc, p_sdst, p_cursor, p_esrc, p_ealpha, E);

    // 5) pull aggregation: warp per dst, register accumulation, no atomics
    k_agg_csr<<<(n * 32 + 255) / 256, 256>>>(p_off, p_esrc, p_ealpha, p_xh, p_agg, n);

    // 6) out = LN(ELU(agg @ W_out^T + b) + x)
    k_gemm2<<<(n + 63) / 64, 256>>>(p_agg, Wout, x, bout, lng, lnb, out, n);
}

// round 9
// speedup vs baseline: 1.0199x; 1.0068x over previous
#include <cuda_runtime.h>
#include <cstdint>

#define NMAX 50000
#define EMAX 400000
#define HEADS 4
#define DIM 64
#define HD 256   // HEADS*DIM

// ---------------- scratch (device globals; no allocation) ----------------
__device__ float g_xh    [(size_t)NMAX * HD];     // projected features [N,256]
__device__ float g_agg   [(size_t)NMAX * HD];     // aggregated messages [N,256]
__device__ float g_ssrc  [(size_t)NMAX * HEADS];
__device__ float g_sdst  [(size_t)NMAX * HEADS];
__device__ int   g_cnt   [NMAX];                  // dst-degree histogram
__device__ int   g_off   [NMAX + 1];              // CSR offsets
__device__ int   g_cursor[NMAX];                  // scatter cursors
__device__ int   g_esrc  [EMAX];                  // src node per sorted edge
__device__ float g_ealpha[(size_t)EMAX * HEADS];  // alpha_exp per sorted edge [*,4]

// ---------------- packed f32x2 helpers (sm_103a) ----------------
__device__ __forceinline__ void ffma2(unsigned long long& acc,
                                      unsigned long long a, unsigned long long b) {
    asm("fma.rn.f32x2 %0, %1, %2, %0;" : "+l"(acc) : "l"(a), "l"(b));
}
__device__ __forceinline__ unsigned long long pack2(float x) {
    unsigned long long r;
    asm("mov.b64 %0, {%1, %1};" : "=l"(r) : "r"(__float_as_uint(x)));
    return r;
}
__device__ __forceinline__ float2 unpack2(unsigned long long v) {
    float2 f;
    asm("mov.b64 {%0, %1}, %2;" : "=f"(f.x), "=f"(f.y) : "l"(v));
    return f;
}

// ---------------- zero histogram ----------------
__global__ void k_hzero(int* __restrict__ cnt, int n) {
    int i = blockIdx.x * blockDim.x + threadIdx.x;
    if (i < n) cnt[i] = 0;
}

// ---------------- histogram of dst ----------------
__global__ void k_hist(const int* __restrict__ ei, int* __restrict__ cnt, int E) {
    int e = blockIdx.x * blockDim.x + threadIdx.x;
    if (e < E) atomicAdd(&cnt[ei[e]], 1);
}

// ---------------- single-block exclusive scan (n up to NMAX) ----------------
__global__ __launch_bounds__(1024) void k_scan(const int* __restrict__ cnt,
                                               int* __restrict__ off,
                                               int* __restrict__ cursor, int n)
{
    __shared__ int warpsum[32];
    const int tid  = threadIdx.x;
    const int lane = tid & 31;
    const int wid  = tid >> 5;
    int base = 0;
    for (int chunk = 0; chunk < n; chunk += 1024) {
        int idx = chunk + tid;
        int v = (idx < n) ? cnt[idx] : 0;
        int x = v;
        #pragma unroll
        for (int o = 1; o < 32; o <<= 1) {
            int y = __shfl_up_sync(0xffffffffu, x, o);
            if (lane >= o) x += y;
        }
        if (lane == 31) warpsum[wid] = x;
        __syncthreads();
        if (wid == 0) {
            int w = (lane < 32) ? warpsum[lane] : 0;
            #pragma unroll
            for (int o = 1; o < 32; o <<= 1) {
                int y = __shfl_up_sync(0xffffffffu, w, o);
                if (lane >= o) w += y;
            }
            warpsum[lane] = w;
        }
        __syncthreads();
        int excl = x - v + (wid > 0 ? warpsum[wid - 1] : 0) + base;
        if (idx < n) { off[idx] = excl; cursor[idx] = excl; }
        int total = warpsum[31];
        __syncthreads();
        base += total;
    }
    if (tid == 0) off[n] = base;
}

// ---------------- GEMM1: xh = x @ W_lin^T, fused attention scores ----------------
// FFMA2 mainloop: acc pairs over column pairs (cg,cg+1),(cg+2,cg+3).
__global__ __launch_bounds__(256) void k_gemm1(
    const float* __restrict__ A,     // x [M,64]
    const float* __restrict__ B,     // W_lin [256,64]
    const float* __restrict__ asrc,  // [4,64]
    const float* __restrict__ adst,  // [4,64]
    float* __restrict__ C,           // xh [M,256]
    float* __restrict__ ssrc, float* __restrict__ sdst, int M)
{
    __shared__ float As[64][68];
    __shared__ float Bs[64][68];
    const int t  = threadIdx.x;
    const int m0 = blockIdx.x * 64;
    const int h  = blockIdx.y;
    const float* Bt = B + (size_t)h * 64 * DIM;
    const int cg = (t & 15) * 4;
    const int rg = (t >> 4) * 4;
    unsigned long long acc01[4] = {0ull, 0ull, 0ull, 0ull};
    unsigned long long acc23[4] = {0ull, 0ull, 0ull, 0ull};

    #pragma unroll
    for (int it = 0; it < 4; ++it) {
        int lin = t + it * 256;
        int r  = lin >> 4;
        int k4 = (lin & 15) * 4;
        float4 v = make_float4(0.f, 0.f, 0.f, 0.f);
        int gr = m0 + r;
        if (gr < M) v = *(const float4*)(A + (size_t)gr * DIM + k4);
        *(float4*)&As[r][k4] = v;
    }
    #pragma unroll
    for (int it = 0; it < 4; ++it) {
        int lin = t + it * 256;
        int c  = lin >> 4;
        int k4 = (lin & 15) * 4;
        float4 v = *(const float4*)(Bt + (size_t)c * DIM + k4);
        Bs[k4 + 0][c] = v.x; Bs[k4 + 1][c] = v.y;
        Bs[k4 + 2][c] = v.z; Bs[k4 + 3][c] = v.w;
    }
    __syncthreads();
    #pragma unroll
    for (int k = 0; k < 64; ++k) {
        ulonglong2 b2 = *(const ulonglong2*)&Bs[k][cg];   // (c0,c1),(c2,c3)
        unsigned long long p0 = pack2(As[rg + 0][k]);
        unsigned long long p1 = pack2(As[rg + 1][k]);
        unsigned long long p2 = pack2(As[rg + 2][k]);
        unsigned long long p3 = pack2(As[rg + 3][k]);
        ffma2(acc01[0], p0, b2.x); ffma2(acc23[0], p0, b2.y);
        ffma2(acc01[1], p1, b2.x); ffma2(acc23[1], p1, b2.y);
        ffma2(acc01[2], p2, b2.x); ffma2(acc23[2], p2, b2.y);
        ffma2(acc01[3], p3, b2.x); ffma2(acc23[3], p3, b2.y);
    }

    float acc[4][4];
    #pragma unroll
    for (int i = 0; i < 4; ++i) {
        float2 lo = unpack2(acc01[i]);
        float2 hi = unpack2(acc23[i]);
        acc[i][0] = lo.x; acc[i][1] = lo.y; acc[i][2] = hi.x; acc[i][3] = hi.y;
    }

    #pragma unroll
    for (int i = 0; i < 4; ++i) {
        int gr = m0 + rg + i;
        if (gr < M) {
            float4 v = make_float4(acc[i][0], acc[i][1], acc[i][2], acc[i][3]);
            *(float4*)(C + (size_t)gr * HD + h * 64 + cg) = v;
        }
    }

    float4 va = __ldg((const float4*)(asrc + h * DIM + cg));
    float4 vd = __ldg((const float4*)(adst + h * DIM + cg));
    float ss[4], sd[4];
    #pragma unroll
    for (int i = 0; i < 4; ++i) {
        ss[i] = acc[i][0] * va.x + acc[i][1] * va.y + acc[i][2] * va.z + acc[i][3] * va.w;
        sd[i] = acc[i][0] * vd.x + acc[i][1] * vd.y + acc[i][2] * vd.z + acc[i][3] * vd.w;
    }
    #pragma unroll
    for (int o = 1; o < 16; o <<= 1) {
        #pragma unroll
        for (int i = 0; i < 4; ++i) {
            ss[i] += __shfl_xor_sync(0xffffffffu, ss[i], o);
            sd[i] += __shfl_xor_sync(0xffffffffu, sd[i], o);
        }
    }
    if ((t & 15) == 0) {
        #pragma unroll
        for (int i = 0; i < 4; ++i) {
            int gr = m0 + rg + i;
            if (gr < M) {
                ssrc[(size_t)gr * HEADS + h] = ss[i];
                sdst[(size_t)gr * HEADS + h] = sd[i];
            }
        }
    }
}

// ---------------- scatter edges into dst-sorted order, alpha computed inline ----------------
__global__ void k_scatter(const int* __restrict__ ei,
                          const float* __restrict__ ssrc, const float* __restrict__ sdst,
                          int* __restrict__ cursor,
                          int* __restrict__ esrc, float* __restrict__ ealpha, int E)
{
    int e = blockIdx.x * blockDim.x + threadIdx.x;
    if (e >= E) return;
    int i = ei[e];        // dst
    int j = ei[E + e];    // src
    float4 sd = *(const float4*)(sdst + (size_t)i * 4);
    float4 ss = *(const float4*)(ssrc + (size_t)j * 4);
    float a0 = sd.x + ss.x; a0 = a0 > 0.f ? a0 : 0.2f * a0;
    float a1 = sd.y + ss.y; a1 = a1 > 0.f ? a1 : 0.2f * a1;
    float a2 = sd.z + ss.z; a2 = a2 > 0.f ? a2 : 0.2f * a2;
    float a3 = sd.w + ss.w; a3 = a3 > 0.f ? a3 : 0.2f * a3;
    int pos = atomicAdd(&cursor[i], 1);
    esrc[pos] = j;
    *(float4*)(ealpha + (size_t)pos * 4) =
        make_float4(expf(a0), expf(a1), expf(a2), expf(a3));
}

// ---------------- CSR aggregation: one warp per dst node ----------------
__global__ __launch_bounds__(256) void k_agg_csr(
    const int* __restrict__ off, const int* __restrict__ esrc,
    const float* __restrict__ ealpha, const float* __restrict__ xh,
    float* __restrict__ agg, int n)
{
    int w    = (blockIdx.x * blockDim.x + threadIdx.x) >> 5;
    int lane = threadIdx.x & 31;
    if (w >= n) return;
    int beg = off[w], end = off[w + 1];
    int head = lane >> 3;
    float acc0 = 0.f, acc1 = 0.f, acc2 = 0.f, acc3 = 0.f;
    float acc4 = 0.f, acc5 = 0.f, acc6 = 0.f, acc7 = 0.f;
    float dsum = 0.f;

    int e = beg;
    int j = 0; float a = 0.f;
    if (e < end) { j = esrc[e]; a = ealpha[(size_t)e * 4 + head]; }
    while (e < end) {
        int jn = 0; float an = 0.f;
        if (e + 1 < end) { jn = esrc[e + 1]; an = ealpha[(size_t)(e + 1) * 4 + head]; }
        const float* s = xh + (size_t)j * HD + lane * 8;
        float4 v0 = *(const float4*)(s);
        float4 v1 = *(const float4*)(s + 4);
        acc0 += a * v0.x; acc1 += a * v0.y; acc2 += a * v0.z; acc3 += a * v0.w;
        acc4 += a * v1.x; acc5 += a * v1.y; acc6 += a * v1.z; acc7 += a * v1.w;
        dsum += a;
        j = jn; a = an; ++e;
    }
    float inv = 1.0f / (dsum + 1e-9f);
    float* d = agg + (size_t)w * HD + lane * 8;
    *(float4*)(d)     = make_float4(acc0 * inv, acc1 * inv, acc2 * inv, acc3 * inv);
    *(float4*)(d + 4) = make_float4(acc4 * inv, acc5 * inv, acc6 * inv, acc7 * inv);
}

// ---------------- GEMM2: out = LN(ELU(agg @ W_out^T + b) + x) ----------------
__global__ __launch_bounds__(256) void k_gemm2(
    const float* __restrict__ A,     // agg [M,256]
    const float* __restrict__ B,     // W_out [64,256]
    const float* __restrict__ x,     // residual [M,64]
    const float* __restrict__ bias,
    const float* __restrict__ lng, const float* __restrict__ lnb,
    float* __restrict__ out, int M)
{
    __shared__ float As[64][68];
    __shared__ float Bs[64][68];
    const int t  = threadIdx.x;
    const int m0 = blockIdx.x * 64;
    const int cg = (t & 15) * 4;
    const int rg = (t >> 4) * 4;
    unsigned long long acc01[4] = {0ull, 0ull, 0ull, 0ull};
    unsigned long long acc23[4] = {0ull, 0ull, 0ull, 0ull};

    for (int kc = 0; kc < HD; kc += 64) {
        #pragma unroll
        for (int it = 0; it < 4; ++it) {
            int lin = t + it * 256;
            int r  = lin >> 4;
            int k4 = (lin & 15) * 4;
            float4 v = make_float4(0.f, 0.f, 0.f, 0.f);
            int gr = m0 + r;
            if (gr < M) v = *(const float4*)(A + (size_t)gr * HD + kc + k4);
            *(float4*)&As[r][k4] = v;
        }
        #pragma unroll
        for (int it = 0; it < 4; ++it) {
            int lin = t + it * 256;
            int c  = lin >> 4;
            int k4 = (lin & 15) * 4;
            float4 v = *(const float4*)(B + (size_t)c * HD + kc + k4);
            Bs[k4 + 0][c] = v.x; Bs[k4 + 1][c] = v.y;
            Bs[k4 + 2][c] = v.z; Bs[k4 + 3][c] = v.w;
        }
        __syncthreads();
        #pragma unroll
        for (int k = 0; k < 64; ++k) {
            ulonglong2 b2 = *(const ulonglong2*)&Bs[k][cg];
            unsigned long long p0 = pack2(As[rg + 0][k]);
            unsigned long long p1 = pack2(As[rg + 1][k]);
            unsigned long long p2 = pack2(As[rg + 2][k]);
            unsigned long long p3 = pack2(As[rg + 3][k]);
            ffma2(acc01[0], p0, b2.x); ffma2(acc23[0], p0, b2.y);
            ffma2(acc01[1], p1, b2.x); ffma2(acc23[1], p1, b2.y);
            ffma2(acc01[2], p2, b2.x); ffma2(acc23[2], p2, b2.y);
            ffma2(acc01[3], p3, b2.x); ffma2(acc23[3], p3, b2.y);
        }
        __syncthreads();
    }

    float acc[4][4];
    #pragma unroll
    for (int i = 0; i < 4; ++i) {
        float2 lo = unpack2(acc01[i]);
        float2 hi = unpack2(acc23[i]);
        acc[i][0] = lo.x; acc[i][1] = lo.y; acc[i][2] = hi.x; acc[i][3] = hi.y;
    }

    float4 bv = __ldg((const float4*)(bias + cg));
    float bb[4] = {bv.x, bv.y, bv.z, bv.w};
    float ls[4], lq[4];
    #pragma unroll
    for (int i = 0; i < 4; ++i) {
        int gr = m0 + rg + i;
        float4 xr = make_float4(0.f, 0.f, 0.f, 0.f);
        if (gr < M) xr = *(const float4*)(x + (size_t)gr * DIM + cg);
        float xa[4] = {xr.x, xr.y, xr.z, xr.w};
        float s = 0.f, q = 0.f;
        #pragma unroll
        for (int c = 0; c < 4; ++c) {
            float v = acc[i][c] + bb[c];
            v = v > 0.f ? v : (expf(v) - 1.0f);   // ELU alpha=1
            float y = v + xa[c];
            acc[i][c] = y;
            s += y; q += y * y;
        }
        ls[i] = s; lq[i] = q;
    }
    #pragma unroll
    for (int o = 1; o < 16; o <<= 1) {
        #pragma unroll
        for (int i = 0; i < 4; ++i) {
            ls[i] += __shfl_xor_sync(0xffffffffu, ls[i], o);
            lq[i] += __shfl_xor_sync(0xffffffffu, lq[i], o);
        }
    }
    float4 gv  = __ldg((const float4*)(lng + cg));
    float4 bvv = __ldg((const float4*)(lnb + cg));
    float gg[4] = {gv.x, gv.y, gv.z, gv.w};
    float lb[4] = {bvv.x, bvv.y, bvv.z, bvv.w};
    #pragma unroll
    for (int i = 0; i < 4; ++i) {
        int gr = m0 + rg + i;
        if (gr < M) {
            float mu  = ls[i] * (1.0f / 64.0f);
            float var = lq[i] * (1.0f / 64.0f) - mu * mu;
            float inv = rsqrtf(var + 1e-5f);
            float4 v;
            v.x = (acc[i][0] - mu) * inv * gg[0] + lb[0];
            v.y = (acc[i][1] - mu) * inv * gg[1] + lb[1];
            v.z = (acc[i][2] - mu) * inv * gg[2] + lb[2];
            v.w = (acc[i][3] - mu) * inv * gg[3] + lb[3];
            *(float4*)(out + (size_t)gr * DIM + cg) = v;
        }
    }
}

// ---------------- launch ----------------
extern "C" void kernel_launch(void* const* d_in, const int* in_sizes, int n_in,
                              void* d_out, int out_size)
{
    const float* x    = (const float*)d_in[0];
    const int*   ei   = (const int*)d_in[1];   // int32 [2,E]
    const float* Wlin = (const float*)d_in[2];
    const float* asrc = (const float*)d_in[3];
    const float* adst = (const float*)d_in[4];
    const float* Wout = (const float*)d_in[5];
    const float* bout = (const float*)d_in[6];
    const float* lng  = (const float*)d_in[7];
    const float* lnb  = (const float*)d_in[8];
    float*       out  = (float*)d_out;

    int n = in_sizes[0] / DIM;
    int E = in_sizes[1] / 2;
    if (n > NMAX) n = NMAX;
    if (E > EMAX) E = EMAX;

    float *p_xh, *p_agg, *p_ssrc, *p_sdst, *p_ealpha;
    int *p_cnt, *p_off, *p_cursor, *p_esrc;
    cudaGetSymbolAddress((void**)&p_xh,     g_xh);
    cudaGetSymbolAddress((void**)&p_agg,    g_agg);
    cudaGetSymbolAddress((void**)&p_ssrc,   g_ssrc);
    cudaGetSymbolAddress((void**)&p_sdst,   g_sdst);
    cudaGetSymbolAddress((void**)&p_cnt,    g_cnt);
    cudaGetSymbolAddress((void**)&p_off,    g_off);
    cudaGetSymbolAddress((void**)&p_cursor, g_cursor);
    cudaGetSymbolAddress((void**)&p_esrc,   g_esrc);
    cudaGetSymbolAddress((void**)&p_ealpha, g_ealpha);

    // 1) dst-degree histogram
    k_hzero<<<(n + 255) / 256, 256>>>(p_cnt, n);
    k_hist <<<(E + 255) / 256, 256>>>(ei, p_cnt, E);

    // 2) CSR offsets (single-block scan)
    k_scan<<<1, 1024>>>(p_cnt, p_off, p_cursor, n);

    // 3) xh = x @ W_lin^T with fused s_src/s_dst (FFMA2 mainloop)
    dim3 g1((n + 63) / 64, HEADS);
    k_gemm1<<<g1, 256>>>(x, Wlin, asrc, adst, p_xh, p_ssrc, p_sdst, n);

    // 4) scatter edges into dst-sorted order with inline alpha
    k_scatter<<<(E + 255) / 256, 256>>>(ei, p_ssrc, p_sdst, p_cursor, p_esrc, p_ealpha, E);

    // 5) pull aggregation: warp per dst, register accumulation, no atomics
    k_agg_csr<<<(n * 32 + 255) / 256, 256>>>(p_off, p_esrc, p_ealpha, p_xh, p_agg, n);

    // 6) out = LN(ELU(agg @ W_out^T + b) + x) (FFMA2 mainloop)
    k_gemm2<<<(n + 63) / 64, 256>>>(p_agg, Wout, x, bout, lng, lnb, out, n);
}